// round 15
// baseline (speedup 1.0000x reference)
#include <cuda_runtime.h>
#include <cuda_fp16.h>
#include <cstdint>
#include <math.h>

#define BATCH 8
#define SEQ   4096
#define DIN   64
#define HID   512
#define M_ROWS (BATCH*SEQ)
#define RSCALE 0.044194173824159216f  /* 1/sqrt(512) */

// ---------------- global scratch (allocation-free rule) ----------------
__device__ __half g_Wt[3*(size_t)HID*DIN];       // W^T fp16: [w][h][d]
__device__ __half g_Q [(size_t)BATCH*SEQ*HID];   // scaled by RSCALE
__device__ __half g_K [(size_t)BATCH*SEQ*HID];
__device__ __half g_Vt[(size_t)BATCH*HID*SEQ];   // V^T [b][h][s]
__device__ __half g_P [(size_t)BATCH*SEQ*SEQ];   // probs fp16 (256 MB)
__device__ float  g_rowsum[BATCH*SEQ];

// ======================= helpers =======================
__device__ __forceinline__ uint32_t smem_u32(const void* p) {
    uint32_t a;
    asm("{ .reg .u64 t; cvta.to.shared.u64 t, %1; cvt.u32.u64 %0, t; }" : "=r"(a) : "l"(p));
    return a;
}
__device__ __forceinline__ void cp16(uint32_t saddr, const void* g) {
    asm volatile("cp.async.cg.shared.global [%0], [%1], 16;"
                 :: "r"(saddr), "l"(__cvta_generic_to_global(g)) : "memory");
}
__device__ __forceinline__ void mma_f16(float* d, const uint32_t* a, const uint32_t* b) {
    asm volatile(
        "mma.sync.aligned.m16n8k16.row.col.f32.f16.f16.f32 "
        "{%0,%1,%2,%3}, {%4,%5,%6,%7}, {%8,%9}, {%0,%1,%2,%3};"
        : "+f"(d[0]), "+f"(d[1]), "+f"(d[2]), "+f"(d[3])
        : "r"(a[0]), "r"(a[1]), "r"(a[2]), "r"(a[3]), "r"(b[0]), "r"(b[1]));
}
__device__ __forceinline__ void ldsm_x4(uint32_t& r0, uint32_t& r1, uint32_t& r2, uint32_t& r3,
                                        uint32_t addr) {
    asm volatile("ldmatrix.sync.aligned.m8n8.x4.shared.b16 {%0,%1,%2,%3}, [%4];"
                 : "=r"(r0), "=r"(r1), "=r"(r2), "=r"(r3) : "r"(addr));
}
__device__ __forceinline__ uint32_t pack2(float a, float b) {
    __half2 h = __floats2half2_rn(a, b);
    return *(uint32_t*)&h;
}

// ---------------- tiny setup: W^T fp16 + zero rowsum ----------------
// blocks [0,48): Wt (12288 threads); [48,64): rowsum zero
__global__ __launch_bounds__(256) void setup_kernel(
    const float* __restrict__ Wq, const float* __restrict__ Wk, const float* __restrict__ Wv)
{
    const int bid = blockIdx.x, tid = threadIdx.x;
    if (bid < 48) {
        int t = bid*256 + tid;
        int w = t / 4096;
        int r = t - w*4096;
        int h = r >> 3;
        int d0 = (r & 7)*8;
        const float* W = (w == 0) ? Wq : (w == 1) ? Wk : Wv;
        float f[8];
        #pragma unroll
        for (int j = 0; j < 8; j++) f[j] = W[(size_t)(d0+j)*HID + h];
        uint4 o;
        o.x = pack2(f[0], f[1]); o.y = pack2(f[2], f[3]);
        o.z = pack2(f[4], f[5]); o.w = pack2(f[6], f[7]);
        *(uint4*)&g_Wt[(size_t)w*HID*DIN + (size_t)h*DIN + d0] = o;
    } else {
        int i = ((bid - 48)*256 + tid)*8;
        #pragma unroll
        for (int j = 0; j < 8; j++) g_rowsum[i+j] = 0.0f;
    }
}

// ---------------- tensor-core QKV projection (direct f32 x load) ----------------
#define PT 136
#define SMEM_PROJ (32768 + PT*128*2)

__global__ __launch_bounds__(256) void qkv_proj_mma_kernel(
    const float* __restrict__ x,
    const float* __restrict__ bq, const float* __restrict__ bk, const float* __restrict__ bv)
{
    extern __shared__ char sm[];
    const uint32_t smem_base = smem_u32(sm);
    const int tid = threadIdx.x;
    const int wid = tid >> 5, lane = tid & 31;
    const int warp_m = wid >> 2, warp_n = wid & 3;
    const int g = lane >> 2, tig = lane & 3;
    const int z = blockIdx.z, mt = blockIdx.y, nt = blockIdx.x;

    const __half* B = g_Wt + (size_t)z*HID*DIN + (size_t)nt*128*DIN;
    const float* bias = (z == 0) ? bq : (z == 1) ? bk : bv;

    // B tile via cp.async (fp16, swizzled 128B rows)
    const int ldrow = tid >> 3, ldf4 = tid & 7;
    const uint32_t sRow = (uint32_t)ldrow*128 + (uint32_t)((ldf4 ^ (ldrow & 7))*16);
    const size_t gOff = (size_t)ldrow*DIN + ldf4*8;
    #pragma unroll
    for (int i = 0; i < 4; i++)
        cp16(smem_base + 16384 + sRow + i*4096, B + gOff + (size_t)i*32*DIN);
    asm volatile("cp.async.commit_group;" ::: "memory");

    // A tile: load x in f32, convert to fp16, swizzled STS (same geometry)
    {
        const float* xt = x + (size_t)mt*128*DIN;
        #pragma unroll
        for (int i = 0; i < 4; i++) {
            int gchunk = tid*4 + i;              // 1024 chunks of 8 halves
            int row = gchunk >> 3, c = gchunk & 7;
            const float* src = xt + (size_t)row*DIN + c*8;
            float4 a = *(const float4*)src;
            float4 b = *(const float4*)(src + 4);
            uint4 o;
            o.x = pack2(a.x, a.y); o.y = pack2(a.z, a.w);
            o.z = pack2(b.x, b.y); o.w = pack2(b.z, b.w);
            *(uint4*)(sm + row*128 + ((c ^ (row & 7))*16)) = o;
        }
    }
    asm volatile("cp.async.wait_group 0;" ::: "memory");
    __syncthreads();

    const int lrow8 = lane & 7;
    const int rowA = lrow8 + 8*((lane >> 3) & 1);
    const int kcA  = lane >> 4;
    const int rowB = lrow8 + 8*(lane >> 4);
    const int kcB  = (lane >> 3) & 1;
    const uint32_t aB = smem_base + (uint32_t)(warp_m*64 + rowA)*128;
    const uint32_t bB = smem_base + 16384 + (uint32_t)(warp_n*32 + rowB)*128;

    float acc[4][4][4];
    #pragma unroll
    for (int i = 0; i < 4; i++)
        #pragma unroll
        for (int j = 0; j < 4; j++)
            #pragma unroll
            for (int v = 0; v < 4; v++) acc[i][j][v] = 0.0f;

    #pragma unroll
    for (int kk = 0; kk < 4; kk++) {
        const uint32_t xA = (uint32_t)(((2*kk + kcA) ^ lrow8)*16);
        const uint32_t xB = (uint32_t)(((2*kk + kcB) ^ lrow8)*16);
        uint32_t af[4][4];
        #pragma unroll
        for (int am = 0; am < 4; am++)
            ldsm_x4(af[am][0], af[am][1], af[am][2], af[am][3], aB + am*2048 + xA);
        uint32_t bf[2][4];
        ldsm_x4(bf[0][0], bf[0][1], bf[0][2], bf[0][3], bB + xB);
        ldsm_x4(bf[1][0], bf[1][1], bf[1][2], bf[1][3], bB + 2048 + xB);
        #pragma unroll
        for (int am = 0; am < 4; am++)
            #pragma unroll
            for (int bn = 0; bn < 4; bn++)
                mma_f16(acc[am][bn], af[am], &bf[bn >> 1][2*(bn & 1)]);
    }

    float b0[4], b1[4];
    #pragma unroll
    for (int bn = 0; bn < 4; bn++) {
        int gcol = nt*128 + warp_n*32 + bn*8 + 2*tig;
        b0[bn] = __ldg(&bias[gcol]);
        b1[bn] = __ldg(&bias[gcol+1]);
    }

    if (z < 2) {
        __half* osel = (z == 0) ? g_Q : g_K;
        const float sc = (z == 0) ? RSCALE : 1.0f;
        #pragma unroll
        for (int am = 0; am < 4; am++) {
            const int r0 = mt*128 + warp_m*64 + am*16 + g;
            const int r1 = r0 + 8;
            #pragma unroll
            for (int bn = 0; bn < 4; bn++) {
                const int gcol = nt*128 + warp_n*32 + bn*8 + 2*tig;
                *(uint32_t*)(osel + (size_t)r0*HID + gcol) =
                    pack2((acc[am][bn][0]+b0[bn])*sc, (acc[am][bn][1]+b1[bn])*sc);
                *(uint32_t*)(osel + (size_t)r1*HID + gcol) =
                    pack2((acc[am][bn][2]+b0[bn])*sc, (acc[am][bn][3]+b1[bn])*sc);
            }
        }
    } else {
        __half* smT = (__half*)(sm + 32768);
        #pragma unroll
        for (int am = 0; am < 4; am++) {
            const int r0 = warp_m*64 + am*16 + g;
            const int r1 = r0 + 8;
            #pragma unroll
            for (int bn = 0; bn < 4; bn++) {
                const int col = warp_n*32 + bn*8 + 2*tig;
                smT[(col  )*PT + r0] = __float2half_rn(acc[am][bn][0]+b0[bn]);
                smT[(col+1)*PT + r0] = __float2half_rn(acc[am][bn][1]+b1[bn]);
                smT[(col  )*PT + r1] = __float2half_rn(acc[am][bn][2]+b0[bn]);
                smT[(col+1)*PT + r1] = __float2half_rn(acc[am][bn][3]+b1[bn]);
            }
        }
        __syncthreads();
        const int bb = mt >> 5;
        const int s0 = (mt*128) & (SEQ-1);
        #pragma unroll
        for (int j = 0; j < 8; j++) {
            int idx = j*256 + tid;
            int h  = idx >> 4;
            int ch = idx & 15;
            uint4 v = *(uint4*)&smT[h*PT + ch*8];
            *(uint4*)&g_Vt[((size_t)bb*HID + nt*128 + h)*SEQ + s0 + ch*8] = v;
        }
    }
}

// ======================= fp16 mma.sync GEMM (spread prefetch) =======================
// C[128,128] per CTA; 128 threads; 4 warps as 2(M) x 2(N); warp tile 64x64.
// K chunked by 64 halves. 3-stage cp.async pipeline, one sync per chunk,
// prefetch cp.asyncs interleaved into the MMA stream (4 per kk-group).
// mode 0: P = fp16(exp(A.B^T)), atomicAdd row sums
// mode 1: O = (A.B^T)/rowsum, fp32
#define KCH 64
#define TILEB (128*128)               // 16384 B
#define STAGEB (2*TILEB)              // 32768 B (A + B)
#define NSTAGE 3
#define SMEM_GEMM (NSTAGE*STAGEB)     // 98304 B

__global__ __launch_bounds__(128, 2) void gemm_f16_kernel(
    const __half* __restrict__ Abase, const __half* __restrict__ Bbase,
    void* __restrict__ Cbase,
    int Kdim, size_t aBatch, size_t bBatch, size_t cBatch, int cld, int mode)
{
    extern __shared__ char sm[];
    const int tid  = threadIdx.x;
    const int wid  = tid >> 5, lane = tid & 31;
    const int warp_m = wid >> 1, warp_n = wid & 1;
    const int g = lane >> 2, tig = lane & 3;
    const int b = blockIdx.z, mt = blockIdx.y, nt = blockIdx.x;

    const __half* A = Abase + (size_t)b*aBatch + (size_t)mt*128*Kdim;
    const __half* B = Bbase + (size_t)b*bBatch + (size_t)nt*128*Kdim;

    const uint32_t smem_base = smem_u32(sm);

    const int ldrow = tid >> 3, ldf4 = tid & 7;
    const uint32_t sRow = (uint32_t)ldrow*128 + (uint32_t)((ldf4 ^ (ldrow & 7)) * 16);
    const size_t aRowOff = (size_t)ldrow*Kdim + ldf4*8;
    const size_t rowStep = (size_t)16*Kdim;

    const int lrow8 = lane & 7;
    const int rowA = lrow8 + 8*((lane >> 3) & 1);
    const int kcA  = lane >> 4;
    const int rowB = lrow8 + 8*(lane >> 4);
    const int kcB  = (lane >> 3) & 1;
    const uint32_t aBase0 = smem_base + (uint32_t)(warp_m*64 + rowA)*128;
    const uint32_t bBase0 = smem_base + TILEB + (uint32_t)(warp_n*64 + rowB)*128;
    uint32_t xA[4], xB[4];
    #pragma unroll
    for (int kk = 0; kk < 4; kk++) {
        xA[kk] = (uint32_t)(((2*kk + kcA) ^ lrow8) * 16);
        xB[kk] = (uint32_t)(((2*kk + kcB) ^ lrow8) * 16);
    }

    float acc[4][8][4];
    #pragma unroll
    for (int i = 0; i < 4; i++)
        #pragma unroll
        for (int j = 0; j < 8; j++)
            #pragma unroll
            for (int v = 0; v < 4; v++) acc[i][j][v] = 0.0f;

    const int NCH = Kdim / KCH;

    // ---- prologue: chunks 0,1 -> stages 0,1 ----
    #pragma unroll
    for (int p = 0; p < 2; p++) {
        const __half* Ak = A + p*KCH;
        const __half* Bk = B + p*KCH;
        uint32_t st = smem_base + (uint32_t)p*STAGEB;
        #pragma unroll
        for (int i = 0; i < 8; i++) {
            cp16(st + sRow + i*2048,         Ak + aRowOff + i*rowStep);
            cp16(st + TILEB + sRow + i*2048, Bk + aRowOff + i*rowStep);
        }
        asm volatile("cp.async.commit_group;" ::: "memory");
    }

    const __half* gA = A + 2*KCH;
    const __half* gB = B + 2*KCH;
    int stR = 0, stW = 2;

    for (int c = 0; c < NCH; ++c) {
        asm volatile("cp.async.wait_group 1;" ::: "memory");   // chunk c resident
        __syncthreads();                                       // reads of stage stW done

        const bool pf = (c + 2 < NCH);
        const uint32_t stA = smem_base + (uint32_t)stW*STAGEB;
        const uint32_t aB = aBase0 + (uint32_t)stR*STAGEB;
        const uint32_t bB = bBase0 + (uint32_t)stR*STAGEB;

        #pragma unroll
        for (int kk = 0; kk < 4; kk++) {
            uint32_t af[4][4];
            #pragma unroll
            for (int am = 0; am < 4; am++)
                ldsm_x4(af[am][0], af[am][1], af[am][2], af[am][3],
                        aB + am*2048 + xA[kk]);
            uint32_t bf[4][4];
            #pragma unroll
            for (int bq = 0; bq < 4; bq++)
                ldsm_x4(bf[bq][0], bf[bq][1], bf[bq][2], bf[bq][3],
                        bB + bq*2048 + xB[kk]);
            if (pf) {
                const int i0 = 2*kk, i1 = 2*kk + 1;
                cp16(stA + sRow + i0*2048,         gA + aRowOff + i0*rowStep);
                cp16(stA + sRow + i1*2048,         gA + aRowOff + i1*rowStep);
                cp16(stA + TILEB + sRow + i0*2048, gB + aRowOff + i0*rowStep);
                cp16(stA + TILEB + sRow + i1*2048, gB + aRowOff + i1*rowStep);
            }
            #pragma unroll
            for (int am = 0; am < 4; am++)
                #pragma unroll
                for (int bn = 0; bn < 8; bn++)
                    mma_f16(acc[am][bn], af[am], &bf[bn >> 1][2*(bn & 1)]);
        }
        if (pf) { gA += KCH; gB += KCH; }
        asm volatile("cp.async.commit_group;" ::: "memory");

        stR = (stR == 2) ? 0 : stR + 1;
        stW = (stW == 2) ? 0 : stW + 1;
    }

    // ================= epilogue =================
    #pragma unroll
    for (int am = 0; am < 4; am++) {
        const int r0 = mt*128 + warp_m*64 + am*16 + g;
        const int r1 = r0 + 8;
        if (mode == 0) {
            __half* C = (__half*)Cbase;
            float s0 = 0.0f, s1 = 0.0f;
            #pragma unroll
            for (int bn = 0; bn < 8; bn++) {
                const int col = nt*128 + warp_n*64 + bn*8 + 2*tig;
                __half h0 = __float2half_rn(__expf(acc[am][bn][0]));
                __half h1 = __float2half_rn(__expf(acc[am][bn][1]));
                __half h2v = __float2half_rn(__expf(acc[am][bn][2]));
                __half h3 = __float2half_rn(__expf(acc[am][bn][3]));
                s0 += __half2float(h0) + __half2float(h1);
                s1 += __half2float(h2v) + __half2float(h3);
                __half2 o0; o0.x = h0;  o0.y = h1;
                __half2 o1; o1.x = h2v; o1.y = h3;
                *(__half2*)(C + (size_t)b*cBatch + (size_t)r0*cld + col) = o0;
                *(__half2*)(C + (size_t)b*cBatch + (size_t)r1*cld + col) = o1;
            }
            s0 += __shfl_xor_sync(0xffffffffu, s0, 1);
            s0 += __shfl_xor_sync(0xffffffffu, s0, 2);
            s1 += __shfl_xor_sync(0xffffffffu, s1, 1);
            s1 += __shfl_xor_sync(0xffffffffu, s1, 2);
            if (tig == 0) {
                atomicAdd(&g_rowsum[b*SEQ + r0], s0);
                atomicAdd(&g_rowsum[b*SEQ + r1], s1);
            }
        } else {
            float* C = (float*)Cbase;
            float inv0 = 1.0f / g_rowsum[b*SEQ + r0];
            float inv1 = 1.0f / g_rowsum[b*SEQ + r1];
            #pragma unroll
            for (int bn = 0; bn < 8; bn++) {
                const int col = nt*128 + warp_n*64 + bn*8 + 2*tig;
                float2 o0; o0.x = acc[am][bn][0]*inv0; o0.y = acc[am][bn][1]*inv0;
                float2 o1; o1.x = acc[am][bn][2]*inv1; o1.y = acc[am][bn][3]*inv1;
                *(float2*)(C + (size_t)b*cBatch + (size_t)r0*cld + col) = o0;
                *(float2*)(C + (size_t)b*cBatch + (size_t)r1*cld + col) = o1;
            }
        }
    }
}

// ---------------- launcher ----------------
extern "C" void kernel_launch(void* const* d_in, const int* in_sizes, int n_in,
                              void* d_out, int out_size)
{
    const float* x  = (const float*)d_in[0];
    const float* Wq = (const float*)d_in[1];
    const float* bq = (const float*)d_in[2];
    const float* Wk = (const float*)d_in[3];
    const float* bk = (const float*)d_in[4];
    const float* Wv = (const float*)d_in[5];
    const float* bv = (const float*)d_in[6];
    float* out = (float*)d_out;

    cudaFuncSetAttribute(qkv_proj_mma_kernel, cudaFuncAttributeMaxDynamicSharedMemorySize, SMEM_PROJ);
    cudaFuncSetAttribute(gemm_f16_kernel, cudaFuncAttributeMaxDynamicSharedMemorySize, SMEM_GEMM);

    __half *g_Q_p, *g_K_p, *g_Vt_p, *g_P_p;
    cudaGetSymbolAddress((void**)&g_Q_p,  g_Q);
    cudaGetSymbolAddress((void**)&g_K_p,  g_K);
    cudaGetSymbolAddress((void**)&g_Vt_p, g_Vt);
    cudaGetSymbolAddress((void**)&g_P_p,  g_P);

    // 1) W^T fp16 + zero rowsums (tiny)
    setup_kernel<<<64, 256>>>(Wq, Wk, Wv);

    // 2) tensor-core QKV projections (x loaded f32 directly)
    qkv_proj_mma_kernel<<<dim3(4, 256, 3), 256, SMEM_PROJ>>>(x, bq, bk, bv);

    // 3) P = exp(Q.K^T), rowsum accumulated
    dim3 sg(SEQ/128, SEQ/128, BATCH);   // (32, 32, 8)
    gemm_f16_kernel<<<sg, 128, SMEM_GEMM>>>(
        g_Q_p, g_K_p, (void*)g_P_p,
        HID, (size_t)SEQ*HID, (size_t)SEQ*HID, (size_t)SEQ*SEQ, SEQ, 0);

    // 4) O = (P.Vt^T) / rowsum
    dim3 og(HID/128, SEQ/128, BATCH);   // (4, 32, 8)
    gemm_f16_kernel<<<og, 128, SMEM_GEMM>>>(
        g_P_p, g_Vt_p, (void*)out,
        SEQ, (size_t)SEQ*SEQ, (size_t)HID*SEQ, (size_t)SEQ*HID, HID, 1);
}

// round 17
// speedup vs baseline: 1.0218x; 1.0218x over previous
#include <cuda_runtime.h>
#include <cuda_fp16.h>
#include <cstdint>
#include <math.h>

#define BATCH 8
#define SEQ   4096
#define DIN   64
#define HID   512
#define M_ROWS (BATCH*SEQ)
#define RSCALE 0.044194173824159216f  /* 1/sqrt(512) */

// ---------------- global scratch (allocation-free rule) ----------------
__device__ __half g_Wt[3*(size_t)HID*DIN];       // W^T fp16: [w][h][d]
__device__ __half g_Q [(size_t)BATCH*SEQ*HID];   // scaled by RSCALE
__device__ __half g_K [(size_t)BATCH*SEQ*HID];
__device__ __half g_Vt[(size_t)BATCH*HID*SEQ];   // V^T [b][h][s]
__device__ __half g_P [(size_t)BATCH*SEQ*SEQ];   // probs fp16 (256 MB)
__device__ float  g_rowsum[BATCH*SEQ];

// ======================= helpers =======================
__device__ __forceinline__ uint32_t smem_u32(const void* p) {
    uint32_t a;
    asm("{ .reg .u64 t; cvta.to.shared.u64 t, %1; cvt.u32.u64 %0, t; }" : "=r"(a) : "l"(p));
    return a;
}
__device__ __forceinline__ void cp16(uint32_t saddr, const void* g) {
    asm volatile("cp.async.cg.shared.global [%0], [%1], 16;"
                 :: "r"(saddr), "l"(__cvta_generic_to_global(g)) : "memory");
}
__device__ __forceinline__ void mma_f16(float* d, const uint32_t* a, const uint32_t* b) {
    asm volatile(
        "mma.sync.aligned.m16n8k16.row.col.f32.f16.f16.f32 "
        "{%0,%1,%2,%3}, {%4,%5,%6,%7}, {%8,%9}, {%0,%1,%2,%3};"
        : "+f"(d[0]), "+f"(d[1]), "+f"(d[2]), "+f"(d[3])
        : "r"(a[0]), "r"(a[1]), "r"(a[2]), "r"(a[3]), "r"(b[0]), "r"(b[1]));
}
__device__ __forceinline__ void ldsm_x4(uint32_t& r0, uint32_t& r1, uint32_t& r2, uint32_t& r3,
                                        uint32_t addr) {
    asm volatile("ldmatrix.sync.aligned.m8n8.x4.shared.b16 {%0,%1,%2,%3}, [%4];"
                 : "=r"(r0), "=r"(r1), "=r"(r2), "=r"(r3) : "r"(addr));
}
__device__ __forceinline__ uint32_t pack2(float a, float b) {
    __half2 h = __floats2half2_rn(a, b);
    return *(uint32_t*)&h;
}

// ---------------- tiny setup: W^T fp16 + zero rowsum ----------------
// blocks [0,48): Wt (12288 threads); [48,64): rowsum zero
__global__ __launch_bounds__(256) void setup_kernel(
    const float* __restrict__ Wq, const float* __restrict__ Wk, const float* __restrict__ Wv)
{
    const int bid = blockIdx.x, tid = threadIdx.x;
    if (bid < 48) {
        int t = bid*256 + tid;
        int w = t / 4096;
        int r = t - w*4096;
        int h = r >> 3;
        int d0 = (r & 7)*8;
        const float* W = (w == 0) ? Wq : (w == 1) ? Wk : Wv;
        float f[8];
        #pragma unroll
        for (int j = 0; j < 8; j++) f[j] = W[(size_t)(d0+j)*HID + h];
        uint4 o;
        o.x = pack2(f[0], f[1]); o.y = pack2(f[2], f[3]);
        o.z = pack2(f[4], f[5]); o.w = pack2(f[6], f[7]);
        *(uint4*)&g_Wt[(size_t)w*HID*DIN + (size_t)h*DIN + d0] = o;
    } else {
        int i = ((bid - 48)*256 + tid)*8;
        #pragma unroll
        for (int j = 0; j < 8; j++) g_rowsum[i+j] = 0.0f;
    }
}

// ---------------- tensor-core QKV projection (x loaded once, nt-loop) ----------------
// grid (mt=256, z=3); 256 threads; per nt iter: C tile 128(s) x 128(h), K=64.
#define PT 136
#define SMEM_PROJ (32768 + PT*128*2)

__global__ __launch_bounds__(256) void qkv_proj_mma_kernel(
    const float* __restrict__ x,
    const float* __restrict__ bq, const float* __restrict__ bk, const float* __restrict__ bv)
{
    extern __shared__ char sm[];
    const uint32_t smem_base = smem_u32(sm);
    const int tid = threadIdx.x;
    const int wid = tid >> 5, lane = tid & 31;
    const int warp_m = wid >> 2, warp_n = wid & 3;
    const int g = lane >> 2, tig = lane & 3;
    const int mt = blockIdx.x, z = blockIdx.y;

    const float* bias = (z == 0) ? bq : (z == 1) ? bk : bv;
    const __half* Wz = g_Wt + (size_t)z*HID*DIN;

    // A tile: load x in f32 ONCE, convert to fp16, swizzled STS
    {
        const float* xt = x + (size_t)mt*128*DIN;
        #pragma unroll
        for (int i = 0; i < 4; i++) {
            int gchunk = tid*4 + i;              // 1024 chunks of 8 halves
            int row = gchunk >> 3, c = gchunk & 7;
            const float* src = xt + (size_t)row*DIN + c*8;
            float4 a = *(const float4*)src;
            float4 b = *(const float4*)(src + 4);
            uint4 o;
            o.x = pack2(a.x, a.y); o.y = pack2(a.z, a.w);
            o.z = pack2(b.x, b.y); o.w = pack2(b.z, b.w);
            *(uint4*)(sm + row*128 + ((c ^ (row & 7))*16)) = o;
        }
    }

    // cp.async geometry for W tiles
    const int ldrow = tid >> 3, ldf4 = tid & 7;
    const uint32_t sRow = (uint32_t)ldrow*128 + (uint32_t)((ldf4 ^ (ldrow & 7))*16);
    const size_t gOff = (size_t)ldrow*DIN + ldf4*8;

    // ldmatrix geometry
    const int lrow8 = lane & 7;
    const int rowA = lrow8 + 8*((lane >> 3) & 1);
    const int kcA  = lane >> 4;
    const int rowB = lrow8 + 8*(lane >> 4);
    const int kcB  = (lane >> 3) & 1;
    const uint32_t aB = smem_base + (uint32_t)(warp_m*64 + rowA)*128;
    const uint32_t bB = smem_base + 16384 + (uint32_t)(warp_n*32 + rowB)*128;

    for (int nt = 0; nt < 4; nt++) {
        __syncthreads();   // prior nt's reads of sW / smT complete (and A STS on first iter)

        // load W tile for this nt
        const __half* B = Wz + (size_t)nt*128*DIN;
        #pragma unroll
        for (int i = 0; i < 4; i++)
            cp16(smem_base + 16384 + sRow + i*4096, B + gOff + (size_t)i*32*DIN);
        asm volatile("cp.async.commit_group;" ::: "memory");
        asm volatile("cp.async.wait_group 0;" ::: "memory");
        __syncthreads();

        float acc[4][4][4];
        #pragma unroll
        for (int i = 0; i < 4; i++)
            #pragma unroll
            for (int j = 0; j < 4; j++)
                #pragma unroll
                for (int v = 0; v < 4; v++) acc[i][j][v] = 0.0f;

        #pragma unroll
        for (int kk = 0; kk < 4; kk++) {
            const uint32_t xA = (uint32_t)(((2*kk + kcA) ^ lrow8)*16);
            const uint32_t xBo = (uint32_t)(((2*kk + kcB) ^ lrow8)*16);
            uint32_t af[4][4];
            #pragma unroll
            for (int am = 0; am < 4; am++)
                ldsm_x4(af[am][0], af[am][1], af[am][2], af[am][3], aB + am*2048 + xA);
            uint32_t bf[2][4];
            ldsm_x4(bf[0][0], bf[0][1], bf[0][2], bf[0][3], bB + xBo);
            ldsm_x4(bf[1][0], bf[1][1], bf[1][2], bf[1][3], bB + 2048 + xBo);
            #pragma unroll
            for (int am = 0; am < 4; am++)
                #pragma unroll
                for (int bn = 0; bn < 4; bn++)
                    mma_f16(acc[am][bn], af[am], &bf[bn >> 1][2*(bn & 1)]);
        }

        float b0[4], b1[4];
        #pragma unroll
        for (int bn = 0; bn < 4; bn++) {
            int gcol = nt*128 + warp_n*32 + bn*8 + 2*tig;
            b0[bn] = __ldg(&bias[gcol]);
            b1[bn] = __ldg(&bias[gcol+1]);
        }

        if (z < 2) {
            __half* osel = (z == 0) ? g_Q : g_K;
            const float sc = (z == 0) ? RSCALE : 1.0f;
            #pragma unroll
            for (int am = 0; am < 4; am++) {
                const int r0 = mt*128 + warp_m*64 + am*16 + g;
                const int r1 = r0 + 8;
                #pragma unroll
                for (int bn = 0; bn < 4; bn++) {
                    const int gcol = nt*128 + warp_n*32 + bn*8 + 2*tig;
                    *(uint32_t*)(osel + (size_t)r0*HID + gcol) =
                        pack2((acc[am][bn][0]+b0[bn])*sc, (acc[am][bn][1]+b1[bn])*sc);
                    *(uint32_t*)(osel + (size_t)r1*HID + gcol) =
                        pack2((acc[am][bn][2]+b0[bn])*sc, (acc[am][bn][3]+b1[bn])*sc);
                }
            }
        } else {
            __half* smT = (__half*)(sm + 32768);
            #pragma unroll
            for (int am = 0; am < 4; am++) {
                const int r0 = warp_m*64 + am*16 + g;
                const int r1 = r0 + 8;
                #pragma unroll
                for (int bn = 0; bn < 4; bn++) {
                    const int col = warp_n*32 + bn*8 + 2*tig;
                    smT[(col  )*PT + r0] = __float2half_rn(acc[am][bn][0]+b0[bn]);
                    smT[(col+1)*PT + r0] = __float2half_rn(acc[am][bn][1]+b1[bn]);
                    smT[(col  )*PT + r1] = __float2half_rn(acc[am][bn][2]+b0[bn]);
                    smT[(col+1)*PT + r1] = __float2half_rn(acc[am][bn][3]+b1[bn]);
                }
            }
            __syncthreads();
            const int bb = mt >> 5;
            const int s0 = (mt*128) & (SEQ-1);
            #pragma unroll
            for (int j = 0; j < 8; j++) {
                int idx = j*256 + tid;
                int h  = idx >> 4;
                int ch = idx & 15;
                uint4 v = *(uint4*)&smT[h*PT + ch*8];
                *(uint4*)&g_Vt[((size_t)bb*HID + nt*128 + h)*SEQ + s0 + ch*8] = v;
            }
        }
    }
}

// ======================= fp16 mma.sync GEMM (R14, byte-identical) =======================
// C[128,128] per CTA; 128 threads; 4 warps as 2(M) x 2(N); warp tile 64x64.
// K chunked by 64 halves. 3-stage cp.async pipeline, one sync per chunk,
// prefetch cp.asyncs interleaved into the MMA stream (4 per kk-group).
// mode 0: P = fp16(exp(A.B^T)), atomicAdd row sums
// mode 1: O = (A.B^T)/rowsum, fp32
#define KCH 64
#define TILEB (128*128)               // 16384 B
#define STAGEB (2*TILEB)              // 32768 B (A + B)
#define NSTAGE 3
#define SMEM_GEMM (NSTAGE*STAGEB)     // 98304 B

__global__ __launch_bounds__(128, 2) void gemm_f16_kernel(
    const __half* __restrict__ Abase, const __half* __restrict__ Bbase,
    void* __restrict__ Cbase,
    int Kdim, size_t aBatch, size_t bBatch, size_t cBatch, int cld, int mode)
{
    extern __shared__ char sm[];
    const int tid  = threadIdx.x;
    const int wid  = tid >> 5, lane = tid & 31;
    const int warp_m = wid >> 1, warp_n = wid & 1;
    const int g = lane >> 2, tig = lane & 3;
    const int b = blockIdx.z, mt = blockIdx.y, nt = blockIdx.x;

    const __half* A = Abase + (size_t)b*aBatch + (size_t)mt*128*Kdim;
    const __half* B = Bbase + (size_t)b*bBatch + (size_t)nt*128*Kdim;

    const uint32_t smem_base = smem_u32(sm);

    const int ldrow = tid >> 3, ldf4 = tid & 7;
    const uint32_t sRow = (uint32_t)ldrow*128 + (uint32_t)((ldf4 ^ (ldrow & 7)) * 16);
    const size_t aRowOff = (size_t)ldrow*Kdim + ldf4*8;
    const size_t rowStep = (size_t)16*Kdim;

    const int lrow8 = lane & 7;
    const int rowA = lrow8 + 8*((lane >> 3) & 1);
    const int kcA  = lane >> 4;
    const int rowB = lrow8 + 8*(lane >> 4);
    const int kcB  = (lane >> 3) & 1;
    const uint32_t aBase0 = smem_base + (uint32_t)(warp_m*64 + rowA)*128;
    const uint32_t bBase0 = smem_base + TILEB + (uint32_t)(warp_n*64 + rowB)*128;
    uint32_t xA[4], xB[4];
    #pragma unroll
    for (int kk = 0; kk < 4; kk++) {
        xA[kk] = (uint32_t)(((2*kk + kcA) ^ lrow8) * 16);
        xB[kk] = (uint32_t)(((2*kk + kcB) ^ lrow8) * 16);
    }

    float acc[4][8][4];
    #pragma unroll
    for (int i = 0; i < 4; i++)
        #pragma unroll
        for (int j = 0; j < 8; j++)
            #pragma unroll
            for (int v = 0; v < 4; v++) acc[i][j][v] = 0.0f;

    const int NCH = Kdim / KCH;

    // ---- prologue: chunks 0,1 -> stages 0,1 ----
    #pragma unroll
    for (int p = 0; p < 2; p++) {
        const __half* Ak = A + p*KCH;
        const __half* Bk = B + p*KCH;
        uint32_t st = smem_base + (uint32_t)p*STAGEB;
        #pragma unroll
        for (int i = 0; i < 8; i++) {
            cp16(st + sRow + i*2048,         Ak + aRowOff + i*rowStep);
            cp16(st + TILEB + sRow + i*2048, Bk + aRowOff + i*rowStep);
        }
        asm volatile("cp.async.commit_group;" ::: "memory");
    }

    const __half* gA = A + 2*KCH;
    const __half* gB = B + 2*KCH;
    int stR = 0, stW = 2;

    for (int c = 0; c < NCH; ++c) {
        asm volatile("cp.async.wait_group 1;" ::: "memory");   // chunk c resident
        __syncthreads();                                       // reads of stage stW done

        const bool pf = (c + 2 < NCH);
        const uint32_t stA = smem_base + (uint32_t)stW*STAGEB;
        const uint32_t aB = aBase0 + (uint32_t)stR*STAGEB;
        const uint32_t bB = bBase0 + (uint32_t)stR*STAGEB;

        #pragma unroll
        for (int kk = 0; kk < 4; kk++) {
            uint32_t af[4][4];
            #pragma unroll
            for (int am = 0; am < 4; am++)
                ldsm_x4(af[am][0], af[am][1], af[am][2], af[am][3],
                        aB + am*2048 + xA[kk]);
            uint32_t bf[4][4];
            #pragma unroll
            for (int bq = 0; bq < 4; bq++)
                ldsm_x4(bf[bq][0], bf[bq][1], bf[bq][2], bf[bq][3],
                        bB + bq*2048 + xB[kk]);
            if (pf) {
                const int i0 = 2*kk, i1 = 2*kk + 1;
                cp16(stA + sRow + i0*2048,         gA + aRowOff + i0*rowStep);
                cp16(stA + sRow + i1*2048,         gA + aRowOff + i1*rowStep);
                cp16(stA + TILEB + sRow + i0*2048, gB + aRowOff + i0*rowStep);
                cp16(stA + TILEB + sRow + i1*2048, gB + aRowOff + i1*rowStep);
            }
            #pragma unroll
            for (int am = 0; am < 4; am++)
                #pragma unroll
                for (int bn = 0; bn < 8; bn++)
                    mma_f16(acc[am][bn], af[am], &bf[bn >> 1][2*(bn & 1)]);
        }
        if (pf) { gA += KCH; gB += KCH; }
        asm volatile("cp.async.commit_group;" ::: "memory");

        stR = (stR == 2) ? 0 : stR + 1;
        stW = (stW == 2) ? 0 : stW + 1;
    }

    // ================= epilogue =================
    #pragma unroll
    for (int am = 0; am < 4; am++) {
        const int r0 = mt*128 + warp_m*64 + am*16 + g;
        const int r1 = r0 + 8;
        if (mode == 0) {
            __half* C = (__half*)Cbase;
            float s0 = 0.0f, s1 = 0.0f;
            #pragma unroll
            for (int bn = 0; bn < 8; bn++) {
                const int col = nt*128 + warp_n*64 + bn*8 + 2*tig;
                __half h0 = __float2half_rn(__expf(acc[am][bn][0]));
                __half h1 = __float2half_rn(__expf(acc[am][bn][1]));
                __half h2v = __float2half_rn(__expf(acc[am][bn][2]));
                __half h3 = __float2half_rn(__expf(acc[am][bn][3]));
                s0 += __half2float(h0) + __half2float(h1);
                s1 += __half2float(h2v) + __half2float(h3);
                __half2 o0; o0.x = h0;  o0.y = h1;
                __half2 o1; o1.x = h2v; o1.y = h3;
                *(__half2*)(C + (size_t)b*cBatch + (size_t)r0*cld + col) = o0;
                *(__half2*)(C + (size_t)b*cBatch + (size_t)r1*cld + col) = o1;
            }
            s0 += __shfl_xor_sync(0xffffffffu, s0, 1);
            s0 += __shfl_xor_sync(0xffffffffu, s0, 2);
            s1 += __shfl_xor_sync(0xffffffffu, s1, 1);
            s1 += __shfl_xor_sync(0xffffffffu, s1, 2);
            if (tig == 0) {
                atomicAdd(&g_rowsum[b*SEQ + r0], s0);
                atomicAdd(&g_rowsum[b*SEQ + r1], s1);
            }
        } else {
            float* C = (float*)Cbase;
            float inv0 = 1.0f / g_rowsum[b*SEQ + r0];
            float inv1 = 1.0f / g_rowsum[b*SEQ + r1];
            #pragma unroll
            for (int bn = 0; bn < 8; bn++) {
                const int col = nt*128 + warp_n*64 + bn*8 + 2*tig;
                float2 o0; o0.x = acc[am][bn][0]*inv0; o0.y = acc[am][bn][1]*inv0;
                float2 o1; o1.x = acc[am][bn][2]*inv1; o1.y = acc[am][bn][3]*inv1;
                *(float2*)(C + (size_t)b*cBatch + (size_t)r0*cld + col) = o0;
                *(float2*)(C + (size_t)b*cBatch + (size_t)r1*cld + col) = o1;
            }
        }
    }
}

// ---------------- launcher ----------------
extern "C" void kernel_launch(void* const* d_in, const int* in_sizes, int n_in,
                              void* d_out, int out_size)
{
    const float* x  = (const float*)d_in[0];
    const float* Wq = (const float*)d_in[1];
    const float* bq = (const float*)d_in[2];
    const float* Wk = (const float*)d_in[3];
    const float* bk = (const float*)d_in[4];
    const float* Wv = (const float*)d_in[5];
    const float* bv = (const float*)d_in[6];
    float* out = (float*)d_out;

    cudaFuncSetAttribute(qkv_proj_mma_kernel, cudaFuncAttributeMaxDynamicSharedMemorySize, SMEM_PROJ);
    cudaFuncSetAttribute(gemm_f16_kernel, cudaFuncAttributeMaxDynamicSharedMemorySize, SMEM_GEMM);

    __half *g_Q_p, *g_K_p, *g_Vt_p, *g_P_p;
    cudaGetSymbolAddress((void**)&g_Q_p,  g_Q);
    cudaGetSymbolAddress((void**)&g_K_p,  g_K);
    cudaGetSymbolAddress((void**)&g_Vt_p, g_Vt);
    cudaGetSymbolAddress((void**)&g_P_p,  g_P);

    // 1) W^T fp16 + zero rowsums (tiny)
    setup_kernel<<<64, 256>>>(Wq, Wk, Wv);

    // 2) tensor-core QKV projections (x loaded once per CTA, nt-loop over W tiles)
    qkv_proj_mma_kernel<<<dim3(256, 3), 256, SMEM_PROJ>>>(x, bq, bk, bv);

    // 3) P = exp(Q.K^T), rowsum accumulated
    dim3 sg(SEQ/128, SEQ/128, BATCH);   // (32, 32, 8)
    gemm_f16_kernel<<<sg, 128, SMEM_GEMM>>>(
        g_Q_p, g_K_p, (void*)g_P_p,
        HID, (size_t)SEQ*HID, (size_t)SEQ*HID, (size_t)SEQ*SEQ, SEQ, 0);

    // 4) O = (P.Vt^T) / rowsum
    dim3 og(HID/128, SEQ/128, BATCH);   // (4, 32, 8)
    gemm_f16_kernel<<<og, 128, SMEM_GEMM>>>(
        g_P_p, g_Vt_p, (void*)out,
        SEQ, (size_t)SEQ*SEQ, (size_t)HID*SEQ, (size_t)SEQ*HID, HID, 1);
}